// round 16
// baseline (speedup 1.0000x reference)
#include <cuda_runtime.h>

#define H 512
#define W 512
#define HW (H * W)
#define BN_EPS 1e-5f
#define RING (4 * W - 4)          // 2044 ring pixels per batch
#define BPX 14                    // border pixels per border block (14*9=126 thr)
#define NBY_MAIN 32               // 512 / 16 rows per main block
#define NBY_EXTRA 10              // 160 border blocks per batch (need 146)

typedef unsigned long long u64;

// Staging (written by prep_kernel) -> copied into __constant__ each launch.
// Layout per tap (20 floats): {w0,w0, w1,w1, ..., w8,w8, pad,pad}
//   [0,1500)     5x5 weights, 75 taps x 20
//   [1500,2040)  3x3 weights, 27 taps x 20
//   [2040,2058)  BN shifts duplicated {sh_k,sh_k}, k=0..8
//   [2058,2060)  pad
__device__ float g_stage[2060];
__constant__ __align__(16) float c_all[2060];

// ---------------- packed f32x2 helpers ----------------
__device__ __forceinline__ u64 pk(float a, float b) {
    u64 d;
    asm("mov.b64 %0, {%1, %2};" : "=l"(d) : "f"(a), "f"(b));
    return d;
}
__device__ __forceinline__ void upk(u64 d, float& a, float& b) {
    asm("mov.b64 {%0, %1}, %2;" : "=f"(a), "=f"(b) : "l"(d));
}
__device__ __forceinline__ void fma2(u64& c, u64 a, u64 b) {
    asm("fma.rn.f32x2 %0, %1, %2, %0;" : "+l"(c) : "l"(a), "l"(b));
}

// ---------------------------------------------------------------------------
// Kernel 1: prep — one staged entry per thread (17 blocks x 128 >= 2060).
// ---------------------------------------------------------------------------
__global__ void prep_kernel(const float* __restrict__ cw,
                            const float* __restrict__ gam,
                            const float* __restrict__ bet,
                            const float* __restrict__ mu,
                            const float* __restrict__ var) {
    int tid = blockIdx.x * blockDim.x + threadIdx.x;
    if (tid >= 2060) return;
    if (tid < 1500) {
        int t5 = tid / 20, kk = tid % 20;
        if (kk >= 18) { g_stage[tid] = 0.f; return; }
        int k = kk >> 1;
        int v = t5 % 5, u = (t5 / 5) % 5, c = t5 / 25;
        float s = gam[k] * rsqrtf(var[k] + BN_EPS);
        float sum = 0.f;
#pragma unroll
        for (int ti = 0; ti < 3; ti++) {
            int di = u - ti;
            if (di < 0 || di > 2) continue;
#pragma unroll
            for (int tj = 0; tj < 3; tj++) {
                int dj = v - tj;
                if (dj < 0 || dj > 2) continue;
                int t = ti * 3 + tj;
                if (c == 0 && t >= 4 && t <= 6) continue;   // replaced rows
                sum += cw[((k * 27 + c * 9 + t) * 3 + di) * 3 + dj];
            }
        }
        g_stage[tid] = s * sum;
    } else if (tid < 2040) {
        int i = tid - 1500;
        int t3 = i / 20, kk = i % 20;
        if (kk >= 18) { g_stage[tid] = 0.f; return; }
        int k = kk >> 1;
        int v = t3 % 3, u = (t3 / 3) % 3, j = t3 / 9;
        float s = gam[k] * rsqrtf(var[k] + BN_EPS);
        g_stage[tid] = s * cw[((k * 27 + 4 + j) * 3 + u) * 3 + v];
    } else if (tid < 2058) {
        int k = (tid - 2040) >> 1;
        float s = gam[k] * rsqrtf(var[k] + BN_EPS);
        g_stage[tid] = bet[k] - mu[k] * s;
    } else {
        g_stage[tid] = 0.f;
    }
}

// ---------------------------------------------------------------------------
// Row loaders over window [w0-2, w0+5]: adjacent pairs adj[t] = {v[t], v[t+1]}.
// Even-t pairs come directly from the 64/128-bit loads; odd-t need 3 movs.
// ---------------------------------------------------------------------------
__device__ __forceinline__ void load_row8_fast(const float* __restrict__ p,
                                               u64 adj[7]) {
    u64 a = *(const u64*)(p - 2);              // {v0,v1}
    ulonglong2 mm = *(const ulonglong2*)(p);   // {v2,v3},{v4,v5} (16B aligned)
    u64 c = *(const u64*)(p + 4);              // {v6,v7}
    adj[0] = a; adj[2] = mm.x; adj[4] = mm.y; adj[6] = c;
    float t0, v1, v2, v3, v4, v5, v6, t1;
    upk(a, t0, v1); upk(mm.x, v2, v3); upk(mm.y, v4, v5); upk(c, v6, t1);
    adj[1] = pk(v1, v2);
    adj[3] = pk(v3, v4);
    adj[5] = pk(v5, v6);
}

__device__ __forceinline__ void load_row8_guard(const float* __restrict__ rowp, int w0,
                                                bool rowok, bool colsafe,
                                                u64 adj[7]) {
    if (rowok && colsafe) {
        load_row8_fast(rowp + w0, adj);
        return;
    }
    float v[8];
    if (rowok) {
#pragma unroll
        for (int i = 0; i < 8; i++) {
            int ww = w0 - 2 + i;
            v[i] = (ww >= 0 && ww < W) ? rowp[ww] : 0.f;
        }
    } else {
#pragma unroll
        for (int i = 0; i < 8; i++) v[i] = 0.f;
    }
#pragma unroll
    for (int i = 0; i < 7; i++) adj[i] = pk(v[i], v[i + 1]);
}

// Apply one tap's 9 duplicated weights from __constant__ at float-offset woff
// to the two pixel pairs (data offsets tv and tv+2).
__device__ __forceinline__ void apply_tap_c(int woff, const u64 adj[7], int tv,
                                            u64 acc[9][2]) {
    const ulonglong2* wq = (const ulonglong2*)&c_all[woff];
    ulonglong2 w01 = wq[0];                    // {w0,w0},{w1,w1}
    ulonglong2 w23 = wq[1];
    ulonglong2 w45 = wq[2];
    ulonglong2 w67 = wq[3];
    u64 w8 = *(const u64*)&c_all[woff + 16];   // {w8,w8}
    u64 d0 = adj[tv], d1 = adj[tv + 2];
    fma2(acc[0][0], w01.x, d0); fma2(acc[0][1], w01.x, d1);
    fma2(acc[1][0], w01.y, d0); fma2(acc[1][1], w01.y, d1);
    fma2(acc[2][0], w23.x, d0); fma2(acc[2][1], w23.x, d1);
    fma2(acc[3][0], w23.y, d0); fma2(acc[3][1], w23.y, d1);
    fma2(acc[4][0], w45.x, d0); fma2(acc[4][1], w45.x, d1);
    fma2(acc[5][0], w45.y, d0); fma2(acc[5][1], w45.y, d1);
    fma2(acc[6][0], w67.x, d0); fma2(acc[6][1], w67.x, d1);
    fma2(acc[7][0], w67.y, d0); fma2(acc[7][1], w67.y, d1);
    fma2(acc[8][0], w8,    d0); fma2(acc[8][1], w8,    d1);
}

// ---------------------------------------------------------------------------
// Kernel 2: fused main + border.
// ---------------------------------------------------------------------------
__global__ __launch_bounds__(128, 6) void cspn_main(
        const float* __restrict__ ker,
        const float* __restrict__ in,
        const float* __restrict__ in0,
        const float* __restrict__ cw,
        const float* __restrict__ gam,
        const float* __restrict__ bet,
        const float* __restrict__ mu,
        const float* __restrict__ var,
        float* __restrict__ out) {
    const int b = blockIdx.z;
    const int tid = threadIdx.y * 8 + threadIdx.x;

    if (blockIdx.y >= NBY_MAIN) {
        // ================= border path =================
        const int bidx = (blockIdx.y - NBY_MAIN) * 16 + blockIdx.x;
        const int base = bidx * BPX;
        if (base >= RING) return;    // dead block (block-uniform)

        __shared__ float sw[2187];
        __shared__ float pacc[BPX * 9 * 9];

        for (int i = tid; i < 2187; i += 128) sw[i] = cw[i];
        __syncthreads();

        const int px   = tid / 9;
        const int didx = tid % 9;
        const int pos  = base + px;
        const bool active = (tid < 126) && (pos < RING);

        float acc[9];
#pragma unroll
        for (int k = 0; k < 9; k++) acc[k] = 0.f;

        if (active) {
            int h, w;
            if (pos < W)          { h = 0;     w = pos; }
            else if (pos < 2 * W) { h = H - 1; w = pos - W; }
            else {
                int p2 = pos - 2 * W;
                h = 1 + (p2 >> 1);
                w = (p2 & 1) ? (W - 1) : 0;
            }
            const float* inb  = in  + (size_t)b * 3 * HW;
            const float* in0b = in0 + (size_t)b * 3 * HW;
            const int dy = didx / 3 - 1, dx = didx % 3 - 1;
            const int qy = h + dy, qx = w + dx;
            const bool qok = (qy >= 0 && qy < H && qx >= 0 && qx < W);
#pragma unroll
            for (int ch = 0; ch < 27; ch++) {
                float val;
                if (ch >= 4 && ch <= 6) {
                    val = qok ? in0b[(ch - 4) * HW + qy * W + qx] : 0.f;
                } else {
                    int c = ch / 9, t = ch % 9;
                    int py = qy + t / 3 - 1, qx2 = qx + t % 3 - 1;
                    bool pok = qok && (py >= 0 && py < H && qx2 >= 0 && qx2 < W);
                    val = pok ? inb[c * HW + py * W + qx2] : 0.f;
                }
#pragma unroll
                for (int k = 0; k < 9; k++)
                    acc[k] = fmaf(sw[(k * 27 + ch) * 9 + didx], val, acc[k]);
            }
        }
        if (tid < 126) {
#pragma unroll
            for (int k = 0; k < 9; k++) pacc[(px * 9 + didx) * 9 + k] = acc[k];
        }
        __syncthreads();

        if (tid < BPX) {
            int pos2 = base + tid;
            if (pos2 < RING) {
                int hh, ww;
                if (pos2 < W)          { hh = 0;     ww = pos2; }
                else if (pos2 < 2 * W) { hh = H - 1; ww = pos2 - W; }
                else {
                    int p2 = pos2 - 2 * W;
                    hh = 1 + (p2 >> 1);
                    ww = (p2 & 1) ? (W - 1) : 0;
                }
                float r = 0.f;
#pragma unroll
                for (int k = 0; k < 9; k++) {
                    float s = 0.f;
#pragma unroll
                    for (int d = 0; d < 9; d++) s += pacc[(tid * 9 + d) * 9 + k];
                    float sc = gam[k] * rsqrtf(var[k] + BN_EPS);
                    float sh = bet[k] - mu[k] * sc;
                    r = fmaf(ker[((size_t)b * 9 + k) * HW + hh * W + ww],
                             fmaf(sc, s, sh), r);
                }
                out[(size_t)b * HW + hh * W + ww] = r;
            }
        }
        return;
    }

    // ================= main path (weights from __constant__) =================
    const int h  = blockIdx.y * 16 + threadIdx.y;
    const int w0 = blockIdx.x * 32 + threadIdx.x * 4;

    // acc[k][j]: packed accum for pixel pair j (pixels 2j,2j+1) of output k.
    // Seeded with the BN shift pair {sh_k, sh_k}.
    u64 acc[9][2];
#pragma unroll
    for (int k = 0; k < 9; k++) {
        u64 shp = *(const u64*)&c_all[2040 + 2 * k];
        acc[k][0] = shp;
        acc[k][1] = shp;
    }

    const float* inb  = in  + (size_t)b * 3 * HW;
    const float* in0b = in0 + (size_t)b * 3 * HW;

    const bool fast = (blockIdx.x >= 1) && (blockIdx.x <= (W / 32) - 2) &&
                      (blockIdx.y >= 1) && (blockIdx.y <= NBY_MAIN - 2);

    if (fast) {
        const float* base5 = inb + (h - 2) * W + w0;
#pragma unroll
        for (int c = 0; c < 3; c++) {
#pragma unroll
            for (int u = 0; u < 5; u++) {
                u64 adj[7];
                load_row8_fast(base5 + c * HW + u * W, adj);
#pragma unroll
                for (int tv = 0; tv < 5; tv++)
                    apply_tap_c(((c * 5 + u) * 5 + tv) * 20, adj, tv, acc);
            }
        }
        const float* base3 = in0b + (h - 1) * W + w0;
#pragma unroll
        for (int j3 = 0; j3 < 3; j3++) {
#pragma unroll
            for (int u = 0; u < 3; u++) {
                u64 adj[7];
                load_row8_fast(base3 + j3 * HW + u * W, adj);
#pragma unroll
                for (int tv = 0; tv < 3; tv++)
                    apply_tap_c(1500 + ((j3 * 3 + u) * 3 + tv) * 20, adj, 1 + tv, acc);
            }
        }
    } else {
        const bool colsafe = (w0 >= 2) && (w0 + 6 <= W);
#pragma unroll 1
        for (int c = 0; c < 3; c++) {
            const float* inc = inb + c * HW;
#pragma unroll 1
            for (int u = 0; u < 5; u++) {
                int r = h + u - 2;
                u64 adj[7];
                load_row8_guard(inc + r * W, w0, (r >= 0 && r < H), colsafe, adj);
#pragma unroll
                for (int tv = 0; tv < 5; tv++)
                    apply_tap_c(((c * 5 + u) * 5 + tv) * 20, adj, tv, acc);
            }
        }
#pragma unroll 1
        for (int j3 = 0; j3 < 3; j3++) {
            const float* inc = in0b + j3 * HW;
#pragma unroll 1
            for (int u = 0; u < 3; u++) {
                int r = h + u - 1;
                u64 adj[7];
                load_row8_guard(inc + r * W, w0, (r >= 0 && r < H), colsafe, adj);
#pragma unroll
                for (int tv = 0; tv < 3; tv++)
                    apply_tap_c(1500 + ((j3 * 3 + u) * 3 + tv) * 20, adj, 1 + tv, acc);
            }
        }
    }

    // ---- epilogue: per-pixel dot with kernel (shift already in acc).
    //      ker pairs {k0,k1},{k2,k3} come free from the 16B-aligned load. ----
    const float* kp = ker + (size_t)b * 9 * HW + h * W + w0;
    u64 r0 = 0ull, r1 = 0ull;
#pragma unroll
    for (int k = 0; k < 9; k++) {
        ulonglong2 kv = *(const ulonglong2*)(kp + k * HW);
        fma2(r0, kv.x, acc[k][0]);
        fma2(r1, kv.y, acc[k][1]);
    }
    float res0, res1, res2, res3;
    upk(r0, res0, res1);
    upk(r1, res2, res3);

    // Interior writes only (ring owned by border blocks).
    if (h >= 1 && h <= H - 2) {
        float* op = out + (size_t)b * HW + h * W + w0;
        if (w0 == 0)          { op[1] = res1; op[2] = res2; op[3] = res3; }
        else if (w0 == W - 4) { op[0] = res0; op[1] = res1; op[2] = res2; }
        else                  { *(float4*)op = make_float4(res0, res1, res2, res3); }
    }
}

// ---------------------------------------------------------------------------
extern "C" void kernel_launch(void* const* d_in, const int* in_sizes, int n_in,
                              void* d_out, int out_size) {
    const float* ker = (const float*)d_in[0];
    const float* in  = (const float*)d_in[1];
    const float* in0 = (const float*)d_in[2];
    const float* cw  = (const float*)d_in[3];
    const float* gam = (const float*)d_in[4];
    const float* bet = (const float*)d_in[5];
    const float* mu  = (const float*)d_in[6];
    const float* var = (const float*)d_in[7];
    float* out = (float*)d_out;

    int bs = in_sizes[0] / (9 * HW);   // batch from kernel tensor size

    prep_kernel<<<17, 128>>>(cw, gam, bet, mu, var);

    // Async D2D copy staged weights into __constant__ (graph-capturable).
    void* stage_ptr = nullptr;
    cudaGetSymbolAddress(&stage_ptr, g_stage);
    cudaMemcpyToSymbolAsync(c_all, stage_ptr, 2060 * sizeof(float), 0,
                            cudaMemcpyDeviceToDevice);

    dim3 blk(8, 16);
    dim3 grd(W / 32, NBY_MAIN + NBY_EXTRA, bs);
    cspn_main<<<grd, blk>>>(ker, in, in0, cw, gam, bet, mu, var, out);
}

// round 17
// speedup vs baseline: 1.0863x; 1.0863x over previous
#include <cuda_runtime.h>

#define H 512
#define W 512
#define HW (H * W)
#define BN_EPS 1e-5f
#define RING (4 * W - 4)          // 2044 ring pixels per batch
#define BPX 14                    // border pixels per border block (14*9=126 thr)
#define NBY_MAIN 32               // 512 / 16 rows per main block
#define NBY_EXTRA 10              // 160 border blocks per batch (need 146)

typedef unsigned long long u64;

// Staging (written by prep_kernel) -> copied into __constant__ each launch.
// Layout per tap (20 floats): {w0,w0, w1,w1, ..., w8,w8, pad,pad}
//   [0,1500)     5x5 weights, 75 taps x 20
//   [1500,2040)  3x3 weights, 27 taps x 20
//   [2040,2058)  BN shifts duplicated {sh_k,sh_k}, k=0..8
//   [2058,2060)  pad
__device__ float g_stage[2060];
__constant__ __align__(16) float c_all[2060];

// ---------------- packed f32x2 helpers ----------------
__device__ __forceinline__ u64 pk(float a, float b) {
    u64 d;
    asm("mov.b64 %0, {%1, %2};" : "=l"(d) : "f"(a), "f"(b));
    return d;
}
__device__ __forceinline__ void upk(u64 d, float& a, float& b) {
    asm("mov.b64 {%0, %1}, %2;" : "=f"(a), "=f"(b) : "l"(d));
}
__device__ __forceinline__ void fma2(u64& c, u64 a, u64 b) {
    asm("fma.rn.f32x2 %0, %1, %2, %0;" : "+l"(c) : "l"(a), "l"(b));
}

// ---------------------------------------------------------------------------
// Kernel 1: prep — one staged entry per thread (17 blocks x 128 >= 2060).
// ---------------------------------------------------------------------------
__global__ void prep_kernel(const float* __restrict__ cw,
                            const float* __restrict__ gam,
                            const float* __restrict__ bet,
                            const float* __restrict__ mu,
                            const float* __restrict__ var) {
    int tid = blockIdx.x * blockDim.x + threadIdx.x;
    if (tid >= 2060) return;
    if (tid < 1500) {
        int t5 = tid / 20, kk = tid % 20;
        if (kk >= 18) { g_stage[tid] = 0.f; return; }
        int k = kk >> 1;
        int v = t5 % 5, u = (t5 / 5) % 5, c = t5 / 25;
        float s = gam[k] * rsqrtf(var[k] + BN_EPS);
        float sum = 0.f;
#pragma unroll
        for (int ti = 0; ti < 3; ti++) {
            int di = u - ti;
            if (di < 0 || di > 2) continue;
#pragma unroll
            for (int tj = 0; tj < 3; tj++) {
                int dj = v - tj;
                if (dj < 0 || dj > 2) continue;
                int t = ti * 3 + tj;
                if (c == 0 && t >= 4 && t <= 6) continue;   // replaced rows
                sum += cw[((k * 27 + c * 9 + t) * 3 + di) * 3 + dj];
            }
        }
        g_stage[tid] = s * sum;
    } else if (tid < 2040) {
        int i = tid - 1500;
        int t3 = i / 20, kk = i % 20;
        if (kk >= 18) { g_stage[tid] = 0.f; return; }
        int k = kk >> 1;
        int v = t3 % 3, u = (t3 / 3) % 3, j = t3 / 9;
        float s = gam[k] * rsqrtf(var[k] + BN_EPS);
        g_stage[tid] = s * cw[((k * 27 + 4 + j) * 3 + u) * 3 + v];
    } else if (tid < 2058) {
        int k = (tid - 2040) >> 1;
        float s = gam[k] * rsqrtf(var[k] + BN_EPS);
        g_stage[tid] = bet[k] - mu[k] * s;
    } else {
        g_stage[tid] = 0.f;
    }
}

// ---------------------------------------------------------------------------
// Row loaders over window [w0-2, w0+5]: adjacent pairs adj[t] = {v[t], v[t+1]}.
// Even-t pairs come directly from the 64/128-bit loads; odd-t need 3 movs.
// ---------------------------------------------------------------------------
__device__ __forceinline__ void load_row8_fast(const float* __restrict__ p,
                                               u64 adj[7]) {
    u64 a = *(const u64*)(p - 2);              // {v0,v1}
    ulonglong2 mm = *(const ulonglong2*)(p);   // {v2,v3},{v4,v5} (16B aligned)
    u64 c = *(const u64*)(p + 4);              // {v6,v7}
    adj[0] = a; adj[2] = mm.x; adj[4] = mm.y; adj[6] = c;
    float t0, v1, v2, v3, v4, v5, v6, t1;
    upk(a, t0, v1); upk(mm.x, v2, v3); upk(mm.y, v4, v5); upk(c, v6, t1);
    adj[1] = pk(v1, v2);
    adj[3] = pk(v3, v4);
    adj[5] = pk(v5, v6);
}

__device__ __forceinline__ void load_row8_guard(const float* __restrict__ rowp, int w0,
                                                bool rowok, bool colsafe,
                                                u64 adj[7]) {
    if (rowok && colsafe) {
        load_row8_fast(rowp + w0, adj);
        return;
    }
    float v[8];
    if (rowok) {
#pragma unroll
        for (int i = 0; i < 8; i++) {
            int ww = w0 - 2 + i;
            v[i] = (ww >= 0 && ww < W) ? rowp[ww] : 0.f;
        }
    } else {
#pragma unroll
        for (int i = 0; i < 8; i++) v[i] = 0.f;
    }
#pragma unroll
    for (int i = 0; i < 7; i++) adj[i] = pk(v[i], v[i + 1]);
}

// Apply one tap's 9 duplicated weights from __constant__ at float-offset woff
// to the two pixel pairs (data offsets tv and tv+2).
__device__ __forceinline__ void apply_tap_c(int woff, const u64 adj[7], int tv,
                                            u64 acc[9][2]) {
    const ulonglong2* wq = (const ulonglong2*)&c_all[woff];
    ulonglong2 w01 = wq[0];                    // {w0,w0},{w1,w1}
    ulonglong2 w23 = wq[1];
    ulonglong2 w45 = wq[2];
    ulonglong2 w67 = wq[3];
    u64 w8 = *(const u64*)&c_all[woff + 16];   // {w8,w8}
    u64 d0 = adj[tv], d1 = adj[tv + 2];
    fma2(acc[0][0], w01.x, d0); fma2(acc[0][1], w01.x, d1);
    fma2(acc[1][0], w01.y, d0); fma2(acc[1][1], w01.y, d1);
    fma2(acc[2][0], w23.x, d0); fma2(acc[2][1], w23.x, d1);
    fma2(acc[3][0], w23.y, d0); fma2(acc[3][1], w23.y, d1);
    fma2(acc[4][0], w45.x, d0); fma2(acc[4][1], w45.x, d1);
    fma2(acc[5][0], w45.y, d0); fma2(acc[5][1], w45.y, d1);
    fma2(acc[6][0], w67.x, d0); fma2(acc[6][1], w67.x, d1);
    fma2(acc[7][0], w67.y, d0); fma2(acc[7][1], w67.y, d1);
    fma2(acc[8][0], w8,    d0); fma2(acc[8][1], w8,    d1);
}

// ---------------------------------------------------------------------------
// Kernel 2: fused main + border.
// ---------------------------------------------------------------------------
__global__ __launch_bounds__(128, 6) void cspn_main(
        const float* __restrict__ ker,
        const float* __restrict__ in,
        const float* __restrict__ in0,
        const float* __restrict__ cw,
        const float* __restrict__ gam,
        const float* __restrict__ bet,
        const float* __restrict__ mu,
        const float* __restrict__ var,
        float* __restrict__ out) {
    const int b = blockIdx.z;
    const int tid = threadIdx.y * 8 + threadIdx.x;

    if (blockIdx.y >= NBY_MAIN) {
        // ================= border path =================
        const int bidx = (blockIdx.y - NBY_MAIN) * 16 + blockIdx.x;
        const int base = bidx * BPX;
        if (base >= RING) return;    // dead block (block-uniform)

        __shared__ float sw[2187];
        __shared__ float pacc[BPX * 9 * 9];

        for (int i = tid; i < 2187; i += 128) sw[i] = cw[i];
        __syncthreads();

        const int px   = tid / 9;
        const int didx = tid % 9;
        const int pos  = base + px;
        const bool active = (tid < 126) && (pos < RING);

        float acc[9];
#pragma unroll
        for (int k = 0; k < 9; k++) acc[k] = 0.f;

        if (active) {
            int h, w;
            if (pos < W)          { h = 0;     w = pos; }
            else if (pos < 2 * W) { h = H - 1; w = pos - W; }
            else {
                int p2 = pos - 2 * W;
                h = 1 + (p2 >> 1);
                w = (p2 & 1) ? (W - 1) : 0;
            }
            const float* inb  = in  + (size_t)b * 3 * HW;
            const float* in0b = in0 + (size_t)b * 3 * HW;
            const int dy = didx / 3 - 1, dx = didx % 3 - 1;
            const int qy = h + dy, qx = w + dx;
            const bool qok = (qy >= 0 && qy < H && qx >= 0 && qx < W);
#pragma unroll
            for (int ch = 0; ch < 27; ch++) {
                float val;
                if (ch >= 4 && ch <= 6) {
                    val = qok ? in0b[(ch - 4) * HW + qy * W + qx] : 0.f;
                } else {
                    int c = ch / 9, t = ch % 9;
                    int py = qy + t / 3 - 1, qx2 = qx + t % 3 - 1;
                    bool pok = qok && (py >= 0 && py < H && qx2 >= 0 && qx2 < W);
                    val = pok ? inb[c * HW + py * W + qx2] : 0.f;
                }
#pragma unroll
                for (int k = 0; k < 9; k++)
                    acc[k] = fmaf(sw[(k * 27 + ch) * 9 + didx], val, acc[k]);
            }
        }
        if (tid < 126) {
#pragma unroll
            for (int k = 0; k < 9; k++) pacc[(px * 9 + didx) * 9 + k] = acc[k];
        }
        __syncthreads();

        if (tid < BPX) {
            int pos2 = base + tid;
            if (pos2 < RING) {
                int hh, ww;
                if (pos2 < W)          { hh = 0;     ww = pos2; }
                else if (pos2 < 2 * W) { hh = H - 1; ww = pos2 - W; }
                else {
                    int p2 = pos2 - 2 * W;
                    hh = 1 + (p2 >> 1);
                    ww = (p2 & 1) ? (W - 1) : 0;
                }
                float r = 0.f;
#pragma unroll
                for (int k = 0; k < 9; k++) {
                    float s = 0.f;
#pragma unroll
                    for (int d = 0; d < 9; d++) s += pacc[(tid * 9 + d) * 9 + k];
                    float sc = gam[k] * rsqrtf(var[k] + BN_EPS);
                    float sh = bet[k] - mu[k] * sc;
                    r = fmaf(ker[((size_t)b * 9 + k) * HW + hh * W + ww],
                             fmaf(sc, s, sh), r);
                }
                out[(size_t)b * HW + hh * W + ww] = r;
            }
        }
        return;
    }

    // ================= main path (weights from __constant__) =================
    const int h  = blockIdx.y * 16 + threadIdx.y;
    const int w0 = blockIdx.x * 32 + threadIdx.x * 4;

    // acc[k][j]: packed accum for pixel pair j (pixels 2j,2j+1) of output k.
    // Seeded with the BN shift pair {sh_k, sh_k}.
    u64 acc[9][2];
#pragma unroll
    for (int k = 0; k < 9; k++) {
        u64 shp = *(const u64*)&c_all[2040 + 2 * k];
        acc[k][0] = shp;
        acc[k][1] = shp;
    }

    const float* inb  = in  + (size_t)b * 3 * HW;
    const float* in0b = in0 + (size_t)b * 3 * HW;

    const bool fast = (blockIdx.x >= 1) && (blockIdx.x <= (W / 32) - 2) &&
                      (blockIdx.y >= 1) && (blockIdx.y <= NBY_MAIN - 2);

    if (fast) {
        const float* base5 = inb + (h - 2) * W + w0;
#pragma unroll
        for (int c = 0; c < 3; c++) {
#pragma unroll
            for (int u = 0; u < 5; u++) {
                u64 adj[7];
                load_row8_fast(base5 + c * HW + u * W, adj);
#pragma unroll
                for (int tv = 0; tv < 5; tv++)
                    apply_tap_c(((c * 5 + u) * 5 + tv) * 20, adj, tv, acc);
            }
        }
        const float* base3 = in0b + (h - 1) * W + w0;
#pragma unroll
        for (int j3 = 0; j3 < 3; j3++) {
#pragma unroll
            for (int u = 0; u < 3; u++) {
                u64 adj[7];
                load_row8_fast(base3 + j3 * HW + u * W, adj);
#pragma unroll
                for (int tv = 0; tv < 3; tv++)
                    apply_tap_c(1500 + ((j3 * 3 + u) * 3 + tv) * 20, adj, 1 + tv, acc);
            }
        }
    } else {
        const bool colsafe = (w0 >= 2) && (w0 + 6 <= W);
#pragma unroll 1
        for (int c = 0; c < 3; c++) {
            const float* inc = inb + c * HW;
#pragma unroll 1
            for (int u = 0; u < 5; u++) {
                int r = h + u - 2;
                u64 adj[7];
                load_row8_guard(inc + r * W, w0, (r >= 0 && r < H), colsafe, adj);
#pragma unroll
                for (int tv = 0; tv < 5; tv++)
                    apply_tap_c(((c * 5 + u) * 5 + tv) * 20, adj, tv, acc);
            }
        }
#pragma unroll 1
        for (int j3 = 0; j3 < 3; j3++) {
            const float* inc = in0b + j3 * HW;
#pragma unroll 1
            for (int u = 0; u < 3; u++) {
                int r = h + u - 1;
                u64 adj[7];
                load_row8_guard(inc + r * W, w0, (r >= 0 && r < H), colsafe, adj);
#pragma unroll
                for (int tv = 0; tv < 3; tv++)
                    apply_tap_c(1500 + ((j3 * 3 + u) * 3 + tv) * 20, adj, 1 + tv, acc);
            }
        }
    }

    // ---- epilogue: per-pixel dot with kernel (shift already in acc).
    //      ker pairs {k0,k1},{k2,k3} come free from the 16B-aligned load. ----
    const float* kp = ker + (size_t)b * 9 * HW + h * W + w0;
    u64 r0 = 0ull, r1 = 0ull;
#pragma unroll
    for (int k = 0; k < 9; k++) {
        ulonglong2 kv = *(const ulonglong2*)(kp + k * HW);
        fma2(r0, kv.x, acc[k][0]);
        fma2(r1, kv.y, acc[k][1]);
    }
    float res0, res1, res2, res3;
    upk(r0, res0, res1);
    upk(r1, res2, res3);

    // Interior writes only (ring owned by border blocks).
    if (h >= 1 && h <= H - 2) {
        float* op = out + (size_t)b * HW + h * W + w0;
        if (w0 == 0)          { op[1] = res1; op[2] = res2; op[3] = res3; }
        else if (w0 == W - 4) { op[0] = res0; op[1] = res1; op[2] = res2; }
        else                  { *(float4*)op = make_float4(res0, res1, res2, res3); }
    }
}

// ---------------------------------------------------------------------------
extern "C" void kernel_launch(void* const* d_in, const int* in_sizes, int n_in,
                              void* d_out, int out_size) {
    const float* ker = (const float*)d_in[0];
    const float* in  = (const float*)d_in[1];
    const float* in0 = (const float*)d_in[2];
    const float* cw  = (const float*)d_in[3];
    const float* gam = (const float*)d_in[4];
    const float* bet = (const float*)d_in[5];
    const float* mu  = (const float*)d_in[6];
    const float* var = (const float*)d_in[7];
    float* out = (float*)d_out;

    int bs = in_sizes[0] / (9 * HW);   // batch from kernel tensor size

    prep_kernel<<<17, 128>>>(cw, gam, bet, mu, var);

    // Async D2D copy staged weights into __constant__ (graph-capturable).
    void* stage_ptr = nullptr;
    cudaGetSymbolAddress(&stage_ptr, g_stage);
    cudaMemcpyToSymbolAsync(c_all, stage_ptr, 2060 * sizeof(float), 0,
                            cudaMemcpyDeviceToDevice);

    dim3 blk(8, 16);
    dim3 grd(W / 32, NBY_MAIN + NBY_EXTRA, bs);
    cspn_main<<<grd, blk>>>(ker, in, in0, cw, gam, bet, mu, var, out);
}